// round 15
// baseline (speedup 1.0000x reference)
#include <cuda_runtime.h>
#include <cuda_bf16.h>
#include <cstdint>

#define NN   50000
#define NE   600000
#define INF  602
#define HID  128
#define OUTF 41
#define KP1  608
#define GBM  128

// ---- tf32 GEMM smem: 2 stages x (A,B) x 128 rows x 36 u32 ----
#define ASTR 36
#define TSTG (128 * ASTR)
#define TSMEM (4 * TSTG * 4)      // 73728 bytes

// ---- bf16 GEMM smem: 2 stages x 4 planes x 128 rows x 80 B ----
#define PLANE 10240
#define STAGE 40960
#define BSMEM 81920

// ---- fat kernel grids ----
#define CNT_GRID  ((NE + 255) / 256)            // 2344
#define PW1_GRID  ((HID * KP1 + 255) / 256)     // 304
#define PW23_GRID ((2 * HID * HID + 255) / 256) // 128

// ---------------- scratch (static device globals; no allocs allowed) --------
__device__ float g_h  [NN * HID];
__device__ __nv_bfloat16 g_xhi[NN * HID];
__device__ __nv_bfloat16 g_xlo[NN * HID];
__device__ __nv_bfloat16 g_x2hi[NN * HID];
__device__ __nv_bfloat16 g_x2lo[NN * HID];
__device__ uint32_t      g_w1t[HID * KP1];
__device__ __nv_bfloat16 g_w2hi[HID * HID];
__device__ __nv_bfloat16 g_w2lo[HID * HID];
__device__ __nv_bfloat16 g_w3hi[HID * HID];
__device__ __nv_bfloat16 g_w3lo[HID * HID];
__device__ int   g_counts[3 * NN];          // [cout | cin | cursor]
__device__ int   g_row_start[NN + 1];
__device__ int   g_esrc[NE];
__device__ float g_rout [NN];
__device__ float g_rout1[NN];   // rout * (1 + 2^-11) tf32 truncation-bias fix
__device__ float g_rin  [NN];

// ---------------- PTX helpers ------------------------------------------------
__device__ __forceinline__ uint32_t s2u(const void* p) {
    uint32_t a;
    asm("{ .reg .u64 t; cvta.to.shared.u64 t, %1; cvt.u32.u64 %0, t; }" : "=r"(a) : "l"(p));
    return a;
}
#define CPA16(dst, src, n) \
    asm volatile("cp.async.cg.shared.global [%0], [%1], 16, %2;" :: "r"(dst), "l"(src), "r"(n))
#define CPA8(dst, src, n) \
    asm volatile("cp.async.ca.shared.global [%0], [%1], 8, %2;" :: "r"(dst), "l"(src), "r"(n))
#define LDSM4(r0, r1, r2, r3, addr) \
    asm volatile("ldmatrix.sync.aligned.m8n8.x4.shared.b16 {%0,%1,%2,%3}, [%4];" \
                 : "=r"(r0), "=r"(r1), "=r"(r2), "=r"(r3) : "r"(addr))
#define MMA_BF16(d, a, b)                                                        \
    asm volatile(                                                                \
        "mma.sync.aligned.m16n8k16.row.col.f32.bf16.bf16.f32 "                   \
        "{%0,%1,%2,%3}, {%4,%5,%6,%7}, {%8,%9}, {%0,%1,%2,%3};"                  \
        : "+f"(d[0]), "+f"(d[1]), "+f"(d[2]), "+f"(d[3])                         \
        : "r"(a[0]), "r"(a[1]), "r"(a[2]), "r"(a[3]), "r"(b[0]), "r"(b[1]))
#define MMA_TF32(d, a, b)                                                        \
    asm volatile(                                                                \
        "mma.sync.aligned.m16n8k8.row.col.f32.tf32.tf32.f32 "                    \
        "{%0,%1,%2,%3}, {%4,%5,%6,%7}, {%8,%9}, {%0,%1,%2,%3};"                  \
        : "+f"(d[0]), "+f"(d[1]), "+f"(d[2]), "+f"(d[3])                         \
        : "r"(a[0]), "r"(a[1]), "r"(a[2]), "r"(a[3]), "r"(b[0]), "r"(b[1]))

__device__ __forceinline__ float bf_lo(uint32_t u) { return __uint_as_float((u & 0xffffu) << 16); }
__device__ __forceinline__ float bf_hi(uint32_t u) { return __uint_as_float(u & 0xffff0000u); }

// ---------------- fat: degree counting + W1 tf32 prep ------------------------
__global__ void fat_count_prepw1(const int* __restrict__ src, const int* __restrict__ dst,
                                 int* __restrict__ cout, int* __restrict__ cin,
                                 const float* __restrict__ W1, uint32_t* __restrict__ w1t) {
    int bx = blockIdx.x;
    int tid = threadIdx.x;
    if (bx < CNT_GRID) {
        int i = bx * 256 + tid;
        if (i < NE) {
            atomicAdd(&cout[src[i]], 1);
            atomicAdd(&cin [dst[i]], 1);
        }
        return;
    }
    int i = (bx - CNT_GRID) * 256 + tid;
    if (i >= HID * KP1) return;
    int n = i / KP1, k = i - n * KP1;
    float v = (k < INF) ? W1[(size_t)k * HID + n] : 0.0f;
    uint32_t r;
    asm("cvt.rna.tf32.f32 %0, %1;" : "=r"(r) : "f"(v));
    w1t[i] = r;
}

// ---------------- scan + rinv merged -----------------------------------------
__global__ void __launch_bounds__(1024)
scan_rinv_kernel(const int* __restrict__ cin, const int* __restrict__ cout,
                 int* __restrict__ row_start, float* __restrict__ rout,
                 float* __restrict__ rout1, float* __restrict__ rin) {
    int tid = threadIdx.x;
    if (blockIdx.x > 0) {
        int i = (blockIdx.x - 1) * 1024 + tid;
        if (i < NN) {
            float ro = rsqrtf(fmaxf((float)cout[i], 1.0f));
            rout [i] = ro;
            rout1[i] = ro * 1.00048828125f;
            rin  [i] = rsqrtf(fmaxf((float)cin[i], 1.0f));
        }
        return;
    }
    __shared__ int warp_sums[32];
    __shared__ int s_carry;
    int lane = tid & 31, wid = tid >> 5;
    if (tid == 0) s_carry = 0;
    __syncthreads();
    for (int base = 0; base < NN; base += 1024) {
        int i = base + tid;
        int v = (i < NN) ? cin[i] : 0;
        int x = v;
#pragma unroll
        for (int off = 1; off < 32; off <<= 1) {
            int t = __shfl_up_sync(0xffffffffu, x, off);
            if (lane >= off) x += t;
        }
        if (lane == 31) warp_sums[wid] = x;
        __syncthreads();
        if (wid == 0) {
            int w = warp_sums[lane];
#pragma unroll
            for (int off = 1; off < 32; off <<= 1) {
                int t = __shfl_up_sync(0xffffffffu, w, off);
                if (lane >= off) w += t;
            }
            warp_sums[lane] = w;
        }
        __syncthreads();
        int warp_off = (wid == 0) ? 0 : warp_sums[wid - 1];
        int carry = s_carry;
        if (i < NN) row_start[i] = carry + warp_off + x - v;
        __syncthreads();
        if (tid == 1023) s_carry = carry + warp_sums[31];
        __syncthreads();
    }
    if (tid == 0) row_start[NN] = NE;
}

// ---------------- fat: CSR fill + W2/W3 bf16 split prep ----------------------
__global__ void fat_fill_prepw23(const int* __restrict__ src, const int* __restrict__ dst,
                                 const int* __restrict__ row_start, int* __restrict__ cursor,
                                 int* __restrict__ esrc,
                                 const float* __restrict__ W2, const float* __restrict__ W3,
                                 __nv_bfloat16* __restrict__ hi2, __nv_bfloat16* __restrict__ lo2,
                                 __nv_bfloat16* __restrict__ hi3, __nv_bfloat16* __restrict__ lo3) {
    int bx = blockIdx.x;
    int tid = threadIdx.x;
    if (bx < CNT_GRID) {
        int i = bx * 256 + tid;
        if (i < NE) {
            int d = dst[i];
            int pos = row_start[d] + atomicAdd(&cursor[d], 1);
            esrc[pos] = src[i];
        }
        return;
    }
    int i = (bx - CNT_GRID) * 256 + tid;
    if (i >= 2 * HID * HID) return;
    int which = i >= HID * HID;
    int j = i - which * HID * HID;
    int n = j >> 7, k = j & 127;
    const float* W = which ? W3 : W2;
    float v = W[(size_t)k * HID + n];
    __nv_bfloat16 h = __float2bfloat16_rn(v);
    __nv_bfloat16 l = __float2bfloat16_rn(v - __bfloat162float(h));
    if (which) { hi3[j] = h; lo3[j] = l; }
    else       { hi2[j] = h; lo2[j] = l; }
}

// ---------------- TF32 GEMM (layer 1): BM=128, 2-stage, parity-split loader --
__global__ void __launch_bounds__(256, 2)
gemm_tf32_kernel(const float* __restrict__ A, const uint32_t* __restrict__ BT,
                 const float* __restrict__ rinv, float* __restrict__ C, int M) {
    extern __shared__ uint32_t smem[];
    uint32_t* As = smem;
    uint32_t* Bs = smem + 2 * TSTG;
    const uint32_t smA = s2u(smem);
    const uint32_t smB = smA + 2 * TSTG * 4;

    const int tid  = threadIdx.x;
    const int lane = tid & 31, wid = tid >> 5;
    const int wm = wid >> 2, wn = wid & 3;
    const int g  = lane >> 2, t = lane & 3;
    const int brow = blockIdx.x * GBM;

    const int  a_lr   = lane >> 1;
    const int  a_half = lane & 1;
    const bool evenw  = (wid < 4);
    const int  lrowA  = evenw ? 2 * (wid * 16 + a_lr)
                              : 2 * ((wid - 4) * 16 + a_lr) + 1;
    const int  agr    = brow + lrowA;
    const bool arv    = (agr < M);
    const float* ap   = A + (size_t)(arv ? agr : 0) * INF;

    const int browl = tid >> 1;
    const int bhalf = tid & 1;
    const uint32_t* bp = BT + (size_t)browl * KP1;

    float acc[4][4][4];
#pragma unroll
    for (int mt = 0; mt < 4; ++mt)
#pragma unroll
        for (int nt = 0; nt < 4; ++nt)
#pragma unroll
            for (int q = 0; q < 4; ++q) acc[mt][nt][q] = 0.0f;

    const int nc = KP1 >> 5;   // 19

    auto load_stage = [&](int s, int kc) {
        uint32_t adst = smA + (s * TSTG + lrowA * ASTR) * 4 + a_half * 64;
        int k0 = kc + a_half * 16;
        if (kc + 32 <= INF) {
            if (evenw) {
                int nb = arv ? 16 : 0;
#pragma unroll
                for (int j = 0; j < 4; ++j)
                    CPA16(adst + j * 16, ap + k0 + j * 4, nb);
            } else {
                int nb = arv ? 8 : 0;
#pragma unroll
                for (int j = 0; j < 8; ++j)
                    CPA8(adst + j * 8, ap + k0 + j * 2, nb);
            }
        } else {
            if (evenw) {
#pragma unroll
                for (int j = 0; j < 4; ++j) {
                    int k = k0 + j * 4;
                    int nb = arv ? min(16, max(0, (INF - k) * 4)) : 0;
                    CPA16(adst + j * 16, ap + (k < INF ? k : 0), nb);
                }
            } else {
#pragma unroll
                for (int j = 0; j < 8; ++j) {
                    int k = k0 + j * 2;
                    int nb = arv ? min(8, max(0, (INF - k) * 4)) : 0;
                    CPA8(adst + j * 8, ap + (k < INF ? k : 0), nb);
                }
            }
        }
        uint32_t bdst = smB + (s * TSTG + browl * ASTR) * 4;
        const uint32_t* bsrc = bp + kc;
#pragma unroll
        for (int j = 0; j < 4; ++j) {
            int c4 = bhalf * 4 + j;
            CPA16(bdst + c4 * 16, bsrc + c4 * 4, 16);
        }
        asm volatile("cp.async.commit_group;");
    };

    load_stage(0, 0);

    for (int c = 0; c < nc; ++c) {
        int s = c & 1;
        if (c + 1 < nc) {
            load_stage(s ^ 1, (c + 1) << 5);
            asm volatile("cp.async.wait_group 1;");
        } else {
            asm volatile("cp.async.wait_group 0;");
        }
        __syncthreads();

        const uint32_t* as = As + s * TSTG;
        const uint32_t* bs = Bs + s * TSTG;
#pragma unroll
        for (int ks = 0; ks < 4; ++ks) {
            int kb = ks * 8;
            uint32_t bf[4][2];
#pragma unroll
            for (int nt = 0; nt < 4; ++nt) {
                int n = wn * 32 + nt * 8 + g;
                bf[nt][0] = bs[n * ASTR + kb + t];
                bf[nt][1] = bs[n * ASTR + kb + t + 4];
            }
#pragma unroll
            for (int mt = 0; mt < 4; ++mt) {
                int r0 = wm * 64 + mt * 16 + g;
                uint32_t af[4] = { as[r0 * ASTR + kb + t],
                                   as[(r0 + 8) * ASTR + kb + t],
                                   as[r0 * ASTR + kb + t + 4],
                                   as[(r0 + 8) * ASTR + kb + t + 4] };
#pragma unroll
                for (int nt = 0; nt < 4; ++nt)
                    MMA_TF32(acc[mt][nt], af, bf[nt]);
            }
        }
        __syncthreads();
    }

#pragma unroll
    for (int mt = 0; mt < 4; ++mt) {
        int r0 = brow + wm * 64 + mt * 16 + g;
        int r1 = r0 + 8;
        float s0 = (r0 < M) ? rinv[r0] : 0.0f;
        float s1 = (r1 < M) ? rinv[r1] : 0.0f;
#pragma unroll
        for (int nt = 0; nt < 4; ++nt) {
            int col = wn * 32 + nt * 8 + 2 * t;
            if (r0 < M)
                *reinterpret_cast<float2*>(&C[(size_t)r0 * HID + col]) =
                    make_float2(acc[mt][nt][0] * s0, acc[mt][nt][1] * s0);
            if (r1 < M)
                *reinterpret_cast<float2*>(&C[(size_t)r1 * HID + col]) =
                    make_float2(acc[mt][nt][2] * s1, acc[mt][nt][3] * s1);
        }
    }
}

// ---------------- split-bf16 3-pass GEMM (layers 2,3) ------------------------
__global__ void __launch_bounds__(256, 2)
gemm_bf16_kernel(const __nv_bfloat16* __restrict__ Ahi, const __nv_bfloat16* __restrict__ Alo,
                 const __nv_bfloat16* __restrict__ Bhi, const __nv_bfloat16* __restrict__ Blo,
                 const float* __restrict__ rinv, float* __restrict__ C) {
    extern __shared__ char smemc[];
    const uint32_t sb = s2u(smemc);

    const int tid  = threadIdx.x;
    const int lane = tid & 31, wid = tid >> 5;
    const int wm = wid >> 2, wn = wid & 3;
    const int g  = lane >> 2, t = lane & 3;
    const int brow = blockIdx.x * GBM;

    const int lrow = tid >> 1, half = tid & 1;
    const int gr = brow + lrow;
    const int av = (gr < NN) ? 16 : 0;
    const size_t arow = (size_t)(gr < NN ? gr : 0) * HID;
    const char* aH = (const char*)Ahi + arow * 2 + half * 32;
    const char* aL = (const char*)Alo + arow * 2 + half * 32;
    const char* bH = (const char*)Bhi + (size_t)lrow * HID * 2 + half * 32;
    const char* bL = (const char*)Blo + (size_t)lrow * HID * 2 + half * 32;
    const uint32_t dst0 = sb + lrow * 80 + half * 32;

    const int rsel = (lane & 7) + ((lane >> 3) & 1) * 8;
    const uint32_t csel = ((uint32_t)(lane >> 4)) * 16;

    float acc[4][4][4];
#pragma unroll
    for (int mt = 0; mt < 4; ++mt)
#pragma unroll
        for (int nt = 0; nt < 4; ++nt)
#pragma unroll
            for (int q = 0; q < 4; ++q) acc[mt][nt][q] = 0.0f;

    const int nc = HID >> 5;   // 4

    auto load_stage = [&](int s, int kc) {
        uint32_t d = dst0 + s * STAGE;
        int go = kc * 2;
        CPA16(d,              aH + go, av); CPA16(d + 16,             aH + go + 16, av);
        CPA16(d + PLANE,      aL + go, av); CPA16(d + PLANE + 16,     aL + go + 16, av);
        CPA16(d + 2 * PLANE,  bH + go, 16); CPA16(d + 2 * PLANE + 16, bH + go + 16, 16);
        CPA16(d + 3 * PLANE,  bL + go, 16); CPA16(d + 3 * PLANE + 16, bL + go + 16, 16);
        asm volatile("cp.async.commit_group;");
    };

    load_stage(0, 0);

    for (int c = 0; c < nc; ++c) {
        int s = c & 1;
        if (c + 1 < nc) {
            load_stage(s ^ 1, (c + 1) << 5);
            asm volatile("cp.async.wait_group 1;");
        } else {
            asm volatile("cp.async.wait_group 0;");
        }
        __syncthreads();

        const uint32_t stg = sb + s * STAGE;
#pragma unroll
        for (int ks = 0; ks < 2; ++ks) {
            const uint32_t coff = ks * 32 + csel;
            uint32_t bh[4][2], bl[4][2];
#pragma unroll
            for (int ntp = 0; ntp < 2; ++ntp) {
                uint32_t ba = stg + 2 * PLANE + (uint32_t)(wn * 32 + ntp * 16 + rsel) * 80 + coff;
                LDSM4(bh[2*ntp][0], bh[2*ntp+1][0], bh[2*ntp][1], bh[2*ntp+1][1], ba);
                LDSM4(bl[2*ntp][0], bl[2*ntp+1][0], bl[2*ntp][1], bl[2*ntp+1][1], ba + PLANE);
            }
#pragma unroll
            for (int mt = 0; mt < 4; ++mt) {
                uint32_t aa = stg + (uint32_t)(wm * 64 + mt * 16 + rsel) * 80 + coff;
                uint32_t ah[4], al[4];
                LDSM4(ah[0], ah[1], ah[2], ah[3], aa);
                LDSM4(al[0], al[1], al[2], al[3], aa + PLANE);
#pragma unroll
                for (int nt = 0; nt < 4; ++nt) {
                    MMA_BF16(acc[mt][nt], ah, bh[nt]);
                    MMA_BF16(acc[mt][nt], ah, bl[nt]);
                    MMA_BF16(acc[mt][nt], al, bh[nt]);
                }
            }
        }
        __syncthreads();
    }

#pragma unroll
    for (int mt = 0; mt < 4; ++mt) {
        int r0 = brow + wm * 64 + mt * 16 + g;
        int r1 = r0 + 8;
        float s0 = (r0 < NN) ? rinv[r0] : 0.0f;
        float s1 = (r1 < NN) ? rinv[r1] : 0.0f;
#pragma unroll
        for (int nt = 0; nt < 4; ++nt) {
            int col = wn * 32 + nt * 8 + 2 * t;
            if (r0 < NN)
                *reinterpret_cast<float2*>(&C[(size_t)r0 * HID + col]) =
                    make_float2(acc[mt][nt][0] * s0, acc[mt][nt][1] * s0);
            if (r1 < NN)
                *reinterpret_cast<float2*>(&C[(size_t)r1 * HID + col]) =
                    make_float2(acc[mt][nt][2] * s1, acc[mt][nt][3] * s1);
        }
    }
}

// ---------------- gather core (unroll 8) -------------------------------------
__device__ __forceinline__ float4 gather_sum(const float4* __restrict__ hv,
                                             const int* __restrict__ esrc,
                                             int beg, int end, int lane) {
    float4 acc = make_float4(0.f, 0.f, 0.f, 0.f);
    int p = beg;
    for (; p + 8 <= end; p += 8) {
        int s0 = esrc[p],     s1 = esrc[p + 1], s2 = esrc[p + 2], s3 = esrc[p + 3];
        int s4 = esrc[p + 4], s5 = esrc[p + 5], s6 = esrc[p + 6], s7 = esrc[p + 7];
        float4 v0 = hv[(size_t)s0 * 32 + lane];
        float4 v1 = hv[(size_t)s1 * 32 + lane];
        float4 v2 = hv[(size_t)s2 * 32 + lane];
        float4 v3 = hv[(size_t)s3 * 32 + lane];
        float4 v4 = hv[(size_t)s4 * 32 + lane];
        float4 v5 = hv[(size_t)s5 * 32 + lane];
        float4 v6 = hv[(size_t)s6 * 32 + lane];
        float4 v7 = hv[(size_t)s7 * 32 + lane];
        acc.x += ((v0.x + v1.x) + (v2.x + v3.x)) + ((v4.x + v5.x) + (v6.x + v7.x));
        acc.y += ((v0.y + v1.y) + (v2.y + v3.y)) + ((v4.y + v5.y) + (v6.y + v7.y));
        acc.z += ((v0.z + v1.z) + (v2.z + v3.z)) + ((v4.z + v5.z) + (v6.z + v7.z));
        acc.w += ((v0.w + v1.w) + (v2.w + v3.w)) + ((v4.w + v5.w) + (v6.w + v7.w));
    }
    for (; p + 4 <= end; p += 4) {
        int s0 = esrc[p], s1 = esrc[p + 1], s2 = esrc[p + 2], s3 = esrc[p + 3];
        float4 v0 = hv[(size_t)s0 * 32 + lane];
        float4 v1 = hv[(size_t)s1 * 32 + lane];
        float4 v2 = hv[(size_t)s2 * 32 + lane];
        float4 v3 = hv[(size_t)s3 * 32 + lane];
        acc.x += (v0.x + v1.x) + (v2.x + v3.x);
        acc.y += (v0.y + v1.y) + (v2.y + v3.y);
        acc.z += (v0.z + v1.z) + (v2.z + v3.z);
        acc.w += (v0.w + v1.w) + (v2.w + v3.w);
    }
    for (; p < end; ++p) {
        int s = esrc[p];
        float4 v = hv[(size_t)s * 32 + lane];
        acc.x += v.x; acc.y += v.y; acc.z += v.z; acc.w += v.w;
    }
    return acc;
}

// ---------------- gather + finalize (layers 1,2) -----------------------------
__global__ void __launch_bounds__(256)
gather_kernel(const float* __restrict__ h, const int* __restrict__ esrc,
              const int* __restrict__ row_start, const float* __restrict__ rin,
              const float* __restrict__ b, uint32_t* __restrict__ ohi,
              uint32_t* __restrict__ olo) {
    int w    = (blockIdx.x * blockDim.x + threadIdx.x) >> 5;
    int lane = threadIdx.x & 31;
    if (w >= NN) return;
    float4 acc = gather_sum(reinterpret_cast<const float4*>(h), esrc,
                            row_start[w], row_start[w + 1], lane);
    float r = rin[w];
    float4 bb = reinterpret_cast<const float4*>(b)[lane];
    float4 o;
    o.x = fmaxf(fmaf(acc.x, r, bb.x), 0.0f);
    o.y = fmaxf(fmaf(acc.y, r, bb.y), 0.0f);
    o.z = fmaxf(fmaf(acc.z, r, bb.z), 0.0f);
    o.w = fmaxf(fmaf(acc.w, r, bb.w), 0.0f);
    __nv_bfloat16 hx = __float2bfloat16_rn(o.x), hy = __float2bfloat16_rn(o.y);
    __nv_bfloat16 hz = __float2bfloat16_rn(o.z), hw = __float2bfloat16_rn(o.w);
    uint32_t h0 = ((uint32_t)__bfloat16_as_ushort(hy) << 16) | __bfloat16_as_ushort(hx);
    uint32_t h1 = ((uint32_t)__bfloat16_as_ushort(hw) << 16) | __bfloat16_as_ushort(hz);
    __nv_bfloat16 lx = __float2bfloat16_rn(o.x - __bfloat162float(hx));
    __nv_bfloat16 ly = __float2bfloat16_rn(o.y - __bfloat162float(hy));
    __nv_bfloat16 lz = __float2bfloat16_rn(o.z - __bfloat162float(hz));
    __nv_bfloat16 lw = __float2bfloat16_rn(o.w - __bfloat162float(hw));
    uint32_t l0 = ((uint32_t)__bfloat16_as_ushort(ly) << 16) | __bfloat16_as_ushort(lx);
    uint32_t l1 = ((uint32_t)__bfloat16_as_ushort(lw) << 16) | __bfloat16_as_ushort(lz);
    size_t base = (size_t)w * 64 + lane * 2;
    ohi[base] = h0; ohi[base + 1] = h1;
    olo[base] = l0; olo[base + 1] = l1;
}

// ---------------- gather 3 + residual + FC head fused ------------------------
// 2 nodes per warp (16/block): halves Wfc smem-staging traffic vs 1/warp.
__global__ void __launch_bounds__(256)
gather_fc_kernel(const float* __restrict__ h, const int* __restrict__ esrc,
                 const int* __restrict__ row_start, const float* __restrict__ rin,
                 const float* __restrict__ b3,
                 const uint32_t* __restrict__ x2hi, const uint32_t* __restrict__ x2lo,
                 const float* __restrict__ Wfc, const float* __restrict__ bfc,
                 float* __restrict__ out) {
    __shared__ float Ws[HID * OUTF];
    __shared__ float bs[64];
    int tid = threadIdx.x;
    for (int i = tid; i < HID * OUTF; i += 256) Ws[i] = Wfc[i];
    if (tid < OUTF) bs[tid] = bfc[tid];
    __syncthreads();

    int lane  = tid & 31;
    int node0 = blockIdx.x * 16 + (tid >> 5) * 2;
    float4 bb = reinterpret_cast<const float4*>(b3)[lane];

#pragma unroll
    for (int i = 0; i < 2; ++i) {
        int w = node0 + i;
        if (w >= NN) return;

        float4 acc = gather_sum(reinterpret_cast<const float4*>(h), esrc,
                                row_start[w], row_start[w + 1], lane);
        float r = rin[w];

        size_t base = (size_t)w * 64 + lane * 2;
        uint32_t H0 = x2hi[base], H1 = x2hi[base + 1];
        uint32_t L0 = x2lo[base], L1 = x2lo[base + 1];

        float y[4];
        y[0] = fmaxf(fmaxf(fmaf(acc.x, r, bb.x), 0.0f) + (bf_lo(H0) + bf_lo(L0)), 0.0f);
        y[1] = fmaxf(fmaxf(fmaf(acc.y, r, bb.y), 0.0f) + (bf_hi(H0) + bf_hi(L0)), 0.0f);
        y[2] = fmaxf(fmaxf(fmaf(acc.z, r, bb.z), 0.0f) + (bf_lo(H1) + bf_lo(L1)), 0.0f);
        y[3] = fmaxf(fmaxf(fmaf(acc.w, r, bb.w), 0.0f) + (bf_hi(H1) + bf_hi(L1)), 0.0f);

        float p0[4] = {0.f, 0.f, 0.f, 0.f};
        float p1[4] = {0.f, 0.f, 0.f, 0.f};
#pragma unroll
        for (int c2 = 0; c2 < 4; ++c2) {
#pragma unroll
            for (int kk = 0; kk < 32; ++kk) {
                float yv = __shfl_sync(0xffffffffu, y[c2], kk);
                int k = kk * 4 + c2;
                p0[c2] = fmaf(yv, Ws[k * OUTF + lane], p0[c2]);
                if (lane < OUTF - 32) p1[c2] = fmaf(yv, Ws[k * OUTF + 32 + lane], p1[c2]);
            }
        }
        out[(size_t)w * OUTF + lane] = (p0[0] + p0[1]) + (p0[2] + p0[3]) + bs[lane];
        if (lane < OUTF - 32)
            out[(size_t)w * OUTF + 32 + lane] =
                (p1[0] + p1[1]) + (p1[2] + p1[3]) + bs[32 + lane];
    }
}

// ---------------- launcher ---------------------------------------------------
extern "C" void kernel_launch(void* const* d_in, const int* in_sizes, int n_in,
                              void* d_out, int out_size) {
    const float* feat = (const float*)d_in[0];
    const int*   src  = (const int*)  d_in[1];
    const int*   dst  = (const int*)  d_in[2];
    const float* W1   = (const float*)d_in[3];
    const float* b1   = (const float*)d_in[4];
    const float* W2   = (const float*)d_in[5];
    const float* b2   = (const float*)d_in[6];
    const float* W3   = (const float*)d_in[7];
    const float* b3   = (const float*)d_in[8];
    const float* Wfc  = (const float*)d_in[9];
    const float* bfc  = (const float*)d_in[10];
    float* out = (float*)d_out;

    float *h, *rout, *rout1, *rin;
    int *counts, *row_start, *esrc;
    uint32_t* w1t;
    __nv_bfloat16 *xhi, *xlo, *x2hi, *x2lo, *w2h, *w2l, *w3h, *w3l;
    cudaGetSymbolAddress((void**)&h,    g_h);
    cudaGetSymbolAddress((void**)&xhi,  g_xhi);
    cudaGetSymbolAddress((void**)&xlo,  g_xlo);
    cudaGetSymbolAddress((void**)&x2hi, g_x2hi);
    cudaGetSymbolAddress((void**)&x2lo, g_x2lo);
    cudaGetSymbolAddress((void**)&w1t,  g_w1t);
    cudaGetSymbolAddress((void**)&w2h,  g_w2hi);
    cudaGetSymbolAddress((void**)&w2l,  g_w2lo);
    cudaGetSymbolAddress((void**)&w3h,  g_w3hi);
    cudaGetSymbolAddress((void**)&w3l,  g_w3lo);
    cudaGetSymbolAddress((void**)&counts,    g_counts);
    cudaGetSymbolAddress((void**)&row_start, g_row_start);
    cudaGetSymbolAddress((void**)&esrc, g_esrc);
    cudaGetSymbolAddress((void**)&rout,  g_rout);
    cudaGetSymbolAddress((void**)&rout1, g_rout1);
    cudaGetSymbolAddress((void**)&rin,   g_rin);

    int* cout_  = counts;
    int* cin_   = counts + NN;
    int* cursor = counts + 2 * NN;

    cudaFuncSetAttribute(gemm_tf32_kernel, cudaFuncAttributeMaxDynamicSharedMemorySize, TSMEM);
    cudaFuncSetAttribute(gemm_bf16_kernel, cudaFuncAttributeMaxDynamicSharedMemorySize, BSMEM);

    const int gemm_grid   = (NN + GBM - 1) / GBM;   // 391
    const int gather_grid = (NN * 32 + 255) / 256;

    cudaMemsetAsync(counts, 0, 3 * NN * sizeof(int));
    // k1: degree count + W1 prep (independent halves, one launch)
    fat_count_prepw1<<<CNT_GRID + PW1_GRID, 256>>>(src, dst, cout_, cin_, W1, w1t);
    // k2: scan (block 0) + rinv (blocks 1..)
    scan_rinv_kernel<<<1 + (NN + 1023) / 1024, 1024>>>(cin_, cout_, row_start,
                                                       rout, rout1, rin);
    // k3: CSR fill + W2/W3 prep (independent halves, one launch)
    fat_fill_prepw23<<<CNT_GRID + PW23_GRID, 256>>>(src, dst, row_start, cursor, esrc,
                                                    W2, W3, w2h, w2l, w3h, w3l);

    // k4 <- profiled: layer-1 tf32 GEMM (parity-split loader; expect ~94 us)
    gemm_tf32_kernel<<<gemm_grid, 256, TSMEM>>>(feat, w1t, rout1, h, NN);

    gather_kernel<<<gather_grid, 256>>>(h, esrc, row_start, rin, b1,
                                        (uint32_t*)xhi, (uint32_t*)xlo);

    // layer 2 (split-bf16; x2 hi/lo doubles as residual branch for the FC head)
    gemm_bf16_kernel<<<gemm_grid, 256, BSMEM>>>(xhi, xlo, w2h, w2l, rout, h);
    gather_kernel<<<gather_grid, 256>>>(h, esrc, row_start, rin, b2,
                                        (uint32_t*)x2hi, (uint32_t*)x2lo);

    // layer 3
    gemm_bf16_kernel<<<gemm_grid, 256, BSMEM>>>(x2hi, x2lo, w3h, w3l, rout, h);

    // gather 3 + residual + FC head fused (2 nodes per warp)
    gather_fc_kernel<<<(NN + 15) / 16, 256>>>(h, esrc, row_start, rin, b3,
                                              (const uint32_t*)x2hi, (const uint32_t*)x2lo,
                                              Wfc, bfc, out);
}

// round 16
// speedup vs baseline: 1.0970x; 1.0970x over previous
#include <cuda_runtime.h>
#include <cuda_bf16.h>
#include <cstdint>

#define NN   50000
#define NE   600000
#define INF  602
#define HID  128
#define OUTF 41
#define KP1  608
#define GBM  128

// ---- tf32 GEMM smem: 2 stages x (A,B) x 128 rows x 36 u32 ----
#define ASTR 36
#define TSTG (128 * ASTR)
#define TSMEM (4 * TSTG * 4)      // 73728 bytes

// ---- bf16 GEMM smem: 2 stages x 4 planes x 128 rows x 80 B ----
#define PLANE 10240
#define STAGE 40960
#define BSMEM 81920

// ---- fat kernel grids ----
#define CNT_GRID  ((NE + 255) / 256)            // 2344
#define PW1_GRID  ((HID * KP1 + 255) / 256)     // 304
#define PW23_GRID ((2 * HID * HID + 255) / 256) // 128

// ---------------- scratch (static device globals; no allocs allowed) --------
__device__ float g_h  [NN * HID];
__device__ __nv_bfloat16 g_xhi[NN * HID];
__device__ __nv_bfloat16 g_xlo[NN * HID];
__device__ __nv_bfloat16 g_x2hi[NN * HID];
__device__ __nv_bfloat16 g_x2lo[NN * HID];
__device__ uint32_t      g_w1t[HID * KP1];
__device__ __nv_bfloat16 g_w2hi[HID * HID];
__device__ __nv_bfloat16 g_w2lo[HID * HID];
__device__ __nv_bfloat16 g_w3hi[HID * HID];
__device__ __nv_bfloat16 g_w3lo[HID * HID];
__device__ int   g_counts[3 * NN];          // [cout | cin | cursor]
__device__ int   g_row_start[NN + 1];
__device__ int   g_esrc[NE];
__device__ float g_rout [NN];
__device__ float g_rout1[NN];   // rout * (1 + 2^-11) tf32 truncation-bias fix
__device__ float g_rin  [NN];

// ---------------- PTX helpers ------------------------------------------------
__device__ __forceinline__ uint32_t s2u(const void* p) {
    uint32_t a;
    asm("{ .reg .u64 t; cvta.to.shared.u64 t, %1; cvt.u32.u64 %0, t; }" : "=r"(a) : "l"(p));
    return a;
}
#define CPA16(dst, src, n) \
    asm volatile("cp.async.cg.shared.global [%0], [%1], 16, %2;" :: "r"(dst), "l"(src), "r"(n))
#define CPA8(dst, src, n) \
    asm volatile("cp.async.ca.shared.global [%0], [%1], 8, %2;" :: "r"(dst), "l"(src), "r"(n))
#define LDSM4(r0, r1, r2, r3, addr) \
    asm volatile("ldmatrix.sync.aligned.m8n8.x4.shared.b16 {%0,%1,%2,%3}, [%4];" \
                 : "=r"(r0), "=r"(r1), "=r"(r2), "=r"(r3) : "r"(addr))
#define MMA_BF16(d, a, b)                                                        \
    asm volatile(                                                                \
        "mma.sync.aligned.m16n8k16.row.col.f32.bf16.bf16.f32 "                   \
        "{%0,%1,%2,%3}, {%4,%5,%6,%7}, {%8,%9}, {%0,%1,%2,%3};"                  \
        : "+f"(d[0]), "+f"(d[1]), "+f"(d[2]), "+f"(d[3])                         \
        : "r"(a[0]), "r"(a[1]), "r"(a[2]), "r"(a[3]), "r"(b[0]), "r"(b[1]))
#define MMA_TF32(d, a, b)                                                        \
    asm volatile(                                                                \
        "mma.sync.aligned.m16n8k8.row.col.f32.tf32.tf32.f32 "                    \
        "{%0,%1,%2,%3}, {%4,%5,%6,%7}, {%8,%9}, {%0,%1,%2,%3};"                  \
        : "+f"(d[0]), "+f"(d[1]), "+f"(d[2]), "+f"(d[3])                         \
        : "r"(a[0]), "r"(a[1]), "r"(a[2]), "r"(a[3]), "r"(b[0]), "r"(b[1]))

__device__ __forceinline__ float bf_lo(uint32_t u) { return __uint_as_float((u & 0xffffu) << 16); }
__device__ __forceinline__ float bf_hi(uint32_t u) { return __uint_as_float(u & 0xffff0000u); }

// ---------------- fat: degree counting + W1 tf32 prep ------------------------
__global__ void fat_count_prepw1(const int* __restrict__ src, const int* __restrict__ dst,
                                 int* __restrict__ cout, int* __restrict__ cin,
                                 const float* __restrict__ W1, uint32_t* __restrict__ w1t) {
    int bx = blockIdx.x;
    int tid = threadIdx.x;
    if (bx < CNT_GRID) {
        int i = bx * 256 + tid;
        if (i < NE) {
            atomicAdd(&cout[src[i]], 1);
            atomicAdd(&cin [dst[i]], 1);
        }
        return;
    }
    int i = (bx - CNT_GRID) * 256 + tid;
    if (i >= HID * KP1) return;
    int n = i / KP1, k = i - n * KP1;
    float v = (k < INF) ? W1[(size_t)k * HID + n] : 0.0f;
    uint32_t r;
    asm("cvt.rna.tf32.f32 %0, %1;" : "=r"(r) : "f"(v));
    w1t[i] = r;
}

// ---------------- scan + rinv merged -----------------------------------------
__global__ void __launch_bounds__(1024)
scan_rinv_kernel(const int* __restrict__ cin, const int* __restrict__ cout,
                 int* __restrict__ row_start, float* __restrict__ rout,
                 float* __restrict__ rout1, float* __restrict__ rin) {
    int tid = threadIdx.x;
    if (blockIdx.x > 0) {
        int i = (blockIdx.x - 1) * 1024 + tid;
        if (i < NN) {
            float ro = rsqrtf(fmaxf((float)cout[i], 1.0f));
            rout [i] = ro;
            rout1[i] = ro * 1.00048828125f;
            rin  [i] = rsqrtf(fmaxf((float)cin[i], 1.0f));
        }
        return;
    }
    __shared__ int warp_sums[32];
    __shared__ int s_carry;
    int lane = tid & 31, wid = tid >> 5;
    if (tid == 0) s_carry = 0;
    __syncthreads();
    for (int base = 0; base < NN; base += 1024) {
        int i = base + tid;
        int v = (i < NN) ? cin[i] : 0;
        int x = v;
#pragma unroll
        for (int off = 1; off < 32; off <<= 1) {
            int t = __shfl_up_sync(0xffffffffu, x, off);
            if (lane >= off) x += t;
        }
        if (lane == 31) warp_sums[wid] = x;
        __syncthreads();
        if (wid == 0) {
            int w = warp_sums[lane];
#pragma unroll
            for (int off = 1; off < 32; off <<= 1) {
                int t = __shfl_up_sync(0xffffffffu, w, off);
                if (lane >= off) w += t;
            }
            warp_sums[lane] = w;
        }
        __syncthreads();
        int warp_off = (wid == 0) ? 0 : warp_sums[wid - 1];
        int carry = s_carry;
        if (i < NN) row_start[i] = carry + warp_off + x - v;
        __syncthreads();
        if (tid == 1023) s_carry = carry + warp_sums[31];
        __syncthreads();
    }
    if (tid == 0) row_start[NN] = NE;
}

// ---------------- fat: CSR fill + W2/W3 bf16 split prep ----------------------
__global__ void fat_fill_prepw23(const int* __restrict__ src, const int* __restrict__ dst,
                                 const int* __restrict__ row_start, int* __restrict__ cursor,
                                 int* __restrict__ esrc,
                                 const float* __restrict__ W2, const float* __restrict__ W3,
                                 __nv_bfloat16* __restrict__ hi2, __nv_bfloat16* __restrict__ lo2,
                                 __nv_bfloat16* __restrict__ hi3, __nv_bfloat16* __restrict__ lo3) {
    int bx = blockIdx.x;
    int tid = threadIdx.x;
    if (bx < CNT_GRID) {
        int i = bx * 256 + tid;
        if (i < NE) {
            int d = dst[i];
            int pos = row_start[d] + atomicAdd(&cursor[d], 1);
            esrc[pos] = src[i];
        }
        return;
    }
    int i = (bx - CNT_GRID) * 256 + tid;
    if (i >= 2 * HID * HID) return;
    int which = i >= HID * HID;
    int j = i - which * HID * HID;
    int n = j >> 7, k = j & 127;
    const float* W = which ? W3 : W2;
    float v = W[(size_t)k * HID + n];
    __nv_bfloat16 h = __float2bfloat16_rn(v);
    __nv_bfloat16 l = __float2bfloat16_rn(v - __bfloat162float(h));
    if (which) { hi3[j] = h; lo3[j] = l; }
    else       { hi2[j] = h; lo2[j] = l; }
}

// ---------------- TF32 GEMM (layer 1): BM=128, 2-stage, parity-split loader --
__global__ void __launch_bounds__(256, 2)
gemm_tf32_kernel(const float* __restrict__ A, const uint32_t* __restrict__ BT,
                 const float* __restrict__ rinv, float* __restrict__ C, int M) {
    extern __shared__ uint32_t smem[];
    uint32_t* As = smem;
    uint32_t* Bs = smem + 2 * TSTG;
    const uint32_t smA = s2u(smem);
    const uint32_t smB = smA + 2 * TSTG * 4;

    const int tid  = threadIdx.x;
    const int lane = tid & 31, wid = tid >> 5;
    const int wm = wid >> 2, wn = wid & 3;
    const int g  = lane >> 2, t = lane & 3;
    const int brow = blockIdx.x * GBM;

    const int  a_lr   = lane >> 1;
    const int  a_half = lane & 1;
    const bool evenw  = (wid < 4);
    const int  lrowA  = evenw ? 2 * (wid * 16 + a_lr)
                              : 2 * ((wid - 4) * 16 + a_lr) + 1;
    const int  agr    = brow + lrowA;
    const bool arv    = (agr < M);
    const float* ap   = A + (size_t)(arv ? agr : 0) * INF;

    const int browl = tid >> 1;
    const int bhalf = tid & 1;
    const uint32_t* bp = BT + (size_t)browl * KP1;

    float acc[4][4][4];
#pragma unroll
    for (int mt = 0; mt < 4; ++mt)
#pragma unroll
        for (int nt = 0; nt < 4; ++nt)
#pragma unroll
            for (int q = 0; q < 4; ++q) acc[mt][nt][q] = 0.0f;

    const int nc = KP1 >> 5;   // 19

    auto load_stage = [&](int s, int kc) {
        uint32_t adst = smA + (s * TSTG + lrowA * ASTR) * 4 + a_half * 64;
        int k0 = kc + a_half * 16;
        if (kc + 32 <= INF) {
            if (evenw) {
                int nb = arv ? 16 : 0;
#pragma unroll
                for (int j = 0; j < 4; ++j)
                    CPA16(adst + j * 16, ap + k0 + j * 4, nb);
            } else {
                int nb = arv ? 8 : 0;
#pragma unroll
                for (int j = 0; j < 8; ++j)
                    CPA8(adst + j * 8, ap + k0 + j * 2, nb);
            }
        } else {
            if (evenw) {
#pragma unroll
                for (int j = 0; j < 4; ++j) {
                    int k = k0 + j * 4;
                    int nb = arv ? min(16, max(0, (INF - k) * 4)) : 0;
                    CPA16(adst + j * 16, ap + (k < INF ? k : 0), nb);
                }
            } else {
#pragma unroll
                for (int j = 0; j < 8; ++j) {
                    int k = k0 + j * 2;
                    int nb = arv ? min(8, max(0, (INF - k) * 4)) : 0;
                    CPA8(adst + j * 8, ap + (k < INF ? k : 0), nb);
                }
            }
        }
        uint32_t bdst = smB + (s * TSTG + browl * ASTR) * 4;
        const uint32_t* bsrc = bp + kc;
#pragma unroll
        for (int j = 0; j < 4; ++j) {
            int c4 = bhalf * 4 + j;
            CPA16(bdst + c4 * 16, bsrc + c4 * 4, 16);
        }
        asm volatile("cp.async.commit_group;");
    };

    load_stage(0, 0);

    for (int c = 0; c < nc; ++c) {
        int s = c & 1;
        if (c + 1 < nc) {
            load_stage(s ^ 1, (c + 1) << 5);
            asm volatile("cp.async.wait_group 1;");
        } else {
            asm volatile("cp.async.wait_group 0;");
        }
        __syncthreads();

        const uint32_t* as = As + s * TSTG;
        const uint32_t* bs = Bs + s * TSTG;
#pragma unroll
        for (int ks = 0; ks < 4; ++ks) {
            int kb = ks * 8;
            uint32_t bf[4][2];
#pragma unroll
            for (int nt = 0; nt < 4; ++nt) {
                int n = wn * 32 + nt * 8 + g;
                bf[nt][0] = bs[n * ASTR + kb + t];
                bf[nt][1] = bs[n * ASTR + kb + t + 4];
            }
#pragma unroll
            for (int mt = 0; mt < 4; ++mt) {
                int r0 = wm * 64 + mt * 16 + g;
                uint32_t af[4] = { as[r0 * ASTR + kb + t],
                                   as[(r0 + 8) * ASTR + kb + t],
                                   as[r0 * ASTR + kb + t + 4],
                                   as[(r0 + 8) * ASTR + kb + t + 4] };
#pragma unroll
                for (int nt = 0; nt < 4; ++nt)
                    MMA_TF32(acc[mt][nt], af, bf[nt]);
            }
        }
        __syncthreads();
    }

#pragma unroll
    for (int mt = 0; mt < 4; ++mt) {
        int r0 = brow + wm * 64 + mt * 16 + g;
        int r1 = r0 + 8;
        float s0 = (r0 < M) ? rinv[r0] : 0.0f;
        float s1 = (r1 < M) ? rinv[r1] : 0.0f;
#pragma unroll
        for (int nt = 0; nt < 4; ++nt) {
            int col = wn * 32 + nt * 8 + 2 * t;
            if (r0 < M)
                *reinterpret_cast<float2*>(&C[(size_t)r0 * HID + col]) =
                    make_float2(acc[mt][nt][0] * s0, acc[mt][nt][1] * s0);
            if (r1 < M)
                *reinterpret_cast<float2*>(&C[(size_t)r1 * HID + col]) =
                    make_float2(acc[mt][nt][2] * s1, acc[mt][nt][3] * s1);
        }
    }
}

// ---------------- split-bf16 3-pass GEMM (layers 2,3) ------------------------
__global__ void __launch_bounds__(256, 2)
gemm_bf16_kernel(const __nv_bfloat16* __restrict__ Ahi, const __nv_bfloat16* __restrict__ Alo,
                 const __nv_bfloat16* __restrict__ Bhi, const __nv_bfloat16* __restrict__ Blo,
                 const float* __restrict__ rinv, float* __restrict__ C) {
    extern __shared__ char smemc[];
    const uint32_t sb = s2u(smemc);

    const int tid  = threadIdx.x;
    const int lane = tid & 31, wid = tid >> 5;
    const int wm = wid >> 2, wn = wid & 3;
    const int g  = lane >> 2, t = lane & 3;
    const int brow = blockIdx.x * GBM;

    const int lrow = tid >> 1, half = tid & 1;
    const int gr = brow + lrow;
    const int av = (gr < NN) ? 16 : 0;
    const size_t arow = (size_t)(gr < NN ? gr : 0) * HID;
    const char* aH = (const char*)Ahi + arow * 2 + half * 32;
    const char* aL = (const char*)Alo + arow * 2 + half * 32;
    const char* bH = (const char*)Bhi + (size_t)lrow * HID * 2 + half * 32;
    const char* bL = (const char*)Blo + (size_t)lrow * HID * 2 + half * 32;
    const uint32_t dst0 = sb + lrow * 80 + half * 32;

    const int rsel = (lane & 7) + ((lane >> 3) & 1) * 8;
    const uint32_t csel = ((uint32_t)(lane >> 4)) * 16;

    float acc[4][4][4];
#pragma unroll
    for (int mt = 0; mt < 4; ++mt)
#pragma unroll
        for (int nt = 0; nt < 4; ++nt)
#pragma unroll
            for (int q = 0; q < 4; ++q) acc[mt][nt][q] = 0.0f;

    const int nc = HID >> 5;   // 4

    auto load_stage = [&](int s, int kc) {
        uint32_t d = dst0 + s * STAGE;
        int go = kc * 2;
        CPA16(d,              aH + go, av); CPA16(d + 16,             aH + go + 16, av);
        CPA16(d + PLANE,      aL + go, av); CPA16(d + PLANE + 16,     aL + go + 16, av);
        CPA16(d + 2 * PLANE,  bH + go, 16); CPA16(d + 2 * PLANE + 16, bH + go + 16, 16);
        CPA16(d + 3 * PLANE,  bL + go, 16); CPA16(d + 3 * PLANE + 16, bL + go + 16, 16);
        asm volatile("cp.async.commit_group;");
    };

    load_stage(0, 0);

    for (int c = 0; c < nc; ++c) {
        int s = c & 1;
        if (c + 1 < nc) {
            load_stage(s ^ 1, (c + 1) << 5);
            asm volatile("cp.async.wait_group 1;");
        } else {
            asm volatile("cp.async.wait_group 0;");
        }
        __syncthreads();

        const uint32_t stg = sb + s * STAGE;
#pragma unroll
        for (int ks = 0; ks < 2; ++ks) {
            const uint32_t coff = ks * 32 + csel;
            uint32_t bh[4][2], bl[4][2];
#pragma unroll
            for (int ntp = 0; ntp < 2; ++ntp) {
                uint32_t ba = stg + 2 * PLANE + (uint32_t)(wn * 32 + ntp * 16 + rsel) * 80 + coff;
                LDSM4(bh[2*ntp][0], bh[2*ntp+1][0], bh[2*ntp][1], bh[2*ntp+1][1], ba);
                LDSM4(bl[2*ntp][0], bl[2*ntp+1][0], bl[2*ntp][1], bl[2*ntp+1][1], ba + PLANE);
            }
#pragma unroll
            for (int mt = 0; mt < 4; ++mt) {
                uint32_t aa = stg + (uint32_t)(wm * 64 + mt * 16 + rsel) * 80 + coff;
                uint32_t ah[4], al[4];
                LDSM4(ah[0], ah[1], ah[2], ah[3], aa);
                LDSM4(al[0], al[1], al[2], al[3], aa + PLANE);
#pragma unroll
                for (int nt = 0; nt < 4; ++nt) {
                    MMA_BF16(acc[mt][nt], ah, bh[nt]);
                    MMA_BF16(acc[mt][nt], ah, bl[nt]);
                    MMA_BF16(acc[mt][nt], al, bh[nt]);
                }
            }
        }
        __syncthreads();
    }

#pragma unroll
    for (int mt = 0; mt < 4; ++mt) {
        int r0 = brow + wm * 64 + mt * 16 + g;
        int r1 = r0 + 8;
        float s0 = (r0 < NN) ? rinv[r0] : 0.0f;
        float s1 = (r1 < NN) ? rinv[r1] : 0.0f;
#pragma unroll
        for (int nt = 0; nt < 4; ++nt) {
            int col = wn * 32 + nt * 8 + 2 * t;
            if (r0 < NN)
                *reinterpret_cast<float2*>(&C[(size_t)r0 * HID + col]) =
                    make_float2(acc[mt][nt][0] * s0, acc[mt][nt][1] * s0);
            if (r1 < NN)
                *reinterpret_cast<float2*>(&C[(size_t)r1 * HID + col]) =
                    make_float2(acc[mt][nt][2] * s1, acc[mt][nt][3] * s1);
        }
    }
}

// ---------------- gather core (unroll 8) -------------------------------------
__device__ __forceinline__ float4 gather_sum(const float4* __restrict__ hv,
                                             const int* __restrict__ esrc,
                                             int beg, int end, int lane) {
    float4 acc = make_float4(0.f, 0.f, 0.f, 0.f);
    int p = beg;
    for (; p + 8 <= end; p += 8) {
        int s0 = esrc[p],     s1 = esrc[p + 1], s2 = esrc[p + 2], s3 = esrc[p + 3];
        int s4 = esrc[p + 4], s5 = esrc[p + 5], s6 = esrc[p + 6], s7 = esrc[p + 7];
        float4 v0 = hv[(size_t)s0 * 32 + lane];
        float4 v1 = hv[(size_t)s1 * 32 + lane];
        float4 v2 = hv[(size_t)s2 * 32 + lane];
        float4 v3 = hv[(size_t)s3 * 32 + lane];
        float4 v4 = hv[(size_t)s4 * 32 + lane];
        float4 v5 = hv[(size_t)s5 * 32 + lane];
        float4 v6 = hv[(size_t)s6 * 32 + lane];
        float4 v7 = hv[(size_t)s7 * 32 + lane];
        acc.x += ((v0.x + v1.x) + (v2.x + v3.x)) + ((v4.x + v5.x) + (v6.x + v7.x));
        acc.y += ((v0.y + v1.y) + (v2.y + v3.y)) + ((v4.y + v5.y) + (v6.y + v7.y));
        acc.z += ((v0.z + v1.z) + (v2.z + v3.z)) + ((v4.z + v5.z) + (v6.z + v7.z));
        acc.w += ((v0.w + v1.w) + (v2.w + v3.w)) + ((v4.w + v5.w) + (v6.w + v7.w));
    }
    for (; p + 4 <= end; p += 4) {
        int s0 = esrc[p], s1 = esrc[p + 1], s2 = esrc[p + 2], s3 = esrc[p + 3];
        float4 v0 = hv[(size_t)s0 * 32 + lane];
        float4 v1 = hv[(size_t)s1 * 32 + lane];
        float4 v2 = hv[(size_t)s2 * 32 + lane];
        float4 v3 = hv[(size_t)s3 * 32 + lane];
        acc.x += (v0.x + v1.x) + (v2.x + v3.x);
        acc.y += (v0.y + v1.y) + (v2.y + v3.y);
        acc.z += (v0.z + v1.z) + (v2.z + v3.z);
        acc.w += (v0.w + v1.w) + (v2.w + v3.w);
    }
    for (; p < end; ++p) {
        int s = esrc[p];
        float4 v = hv[(size_t)s * 32 + lane];
        acc.x += v.x; acc.y += v.y; acc.z += v.z; acc.w += v.w;
    }
    return acc;
}

// ---------------- gather + finalize (layers 1,2) -----------------------------
__global__ void __launch_bounds__(256)
gather_kernel(const float* __restrict__ h, const int* __restrict__ esrc,
              const int* __restrict__ row_start, const float* __restrict__ rin,
              const float* __restrict__ b, uint32_t* __restrict__ ohi,
              uint32_t* __restrict__ olo) {
    int w    = (blockIdx.x * blockDim.x + threadIdx.x) >> 5;
    int lane = threadIdx.x & 31;
    if (w >= NN) return;
    float4 acc = gather_sum(reinterpret_cast<const float4*>(h), esrc,
                            row_start[w], row_start[w + 1], lane);
    float r = rin[w];
    float4 bb = reinterpret_cast<const float4*>(b)[lane];
    float4 o;
    o.x = fmaxf(fmaf(acc.x, r, bb.x), 0.0f);
    o.y = fmaxf(fmaf(acc.y, r, bb.y), 0.0f);
    o.z = fmaxf(fmaf(acc.z, r, bb.z), 0.0f);
    o.w = fmaxf(fmaf(acc.w, r, bb.w), 0.0f);
    __nv_bfloat16 hx = __float2bfloat16_rn(o.x), hy = __float2bfloat16_rn(o.y);
    __nv_bfloat16 hz = __float2bfloat16_rn(o.z), hw = __float2bfloat16_rn(o.w);
    uint32_t h0 = ((uint32_t)__bfloat16_as_ushort(hy) << 16) | __bfloat16_as_ushort(hx);
    uint32_t h1 = ((uint32_t)__bfloat16_as_ushort(hw) << 16) | __bfloat16_as_ushort(hz);
    __nv_bfloat16 lx = __float2bfloat16_rn(o.x - __bfloat162float(hx));
    __nv_bfloat16 ly = __float2bfloat16_rn(o.y - __bfloat162float(hy));
    __nv_bfloat16 lz = __float2bfloat16_rn(o.z - __bfloat162float(hz));
    __nv_bfloat16 lw = __float2bfloat16_rn(o.w - __bfloat162float(hw));
    uint32_t l0 = ((uint32_t)__bfloat16_as_ushort(ly) << 16) | __bfloat16_as_ushort(lx);
    uint32_t l1 = ((uint32_t)__bfloat16_as_ushort(lw) << 16) | __bfloat16_as_ushort(lz);
    size_t base = (size_t)w * 64 + lane * 2;
    ohi[base] = h0; ohi[base + 1] = h1;
    olo[base] = l0; olo[base + 1] = l1;
}

// ---------------- gather 3 + residual + FC head fused ------------------------
// One node per warp (measured-best); x2 reconstructed from bf16 hi/lo planes.
__global__ void __launch_bounds__(256)
gather_fc_kernel(const float* __restrict__ h, const int* __restrict__ esrc,
                 const int* __restrict__ row_start, const float* __restrict__ rin,
                 const float* __restrict__ b3,
                 const uint32_t* __restrict__ x2hi, const uint32_t* __restrict__ x2lo,
                 const float* __restrict__ Wfc, const float* __restrict__ bfc,
                 float* __restrict__ out) {
    __shared__ float Ws[HID * OUTF];
    __shared__ float bs[64];
    int tid = threadIdx.x;
    for (int i = tid; i < HID * OUTF; i += 256) Ws[i] = Wfc[i];
    if (tid < OUTF) bs[tid] = bfc[tid];
    __syncthreads();

    int w    = blockIdx.x * 8 + (tid >> 5);
    int lane = tid & 31;
    if (w >= NN) return;

    float4 acc = gather_sum(reinterpret_cast<const float4*>(h), esrc,
                            row_start[w], row_start[w + 1], lane);
    float r = rin[w];
    float4 bb = reinterpret_cast<const float4*>(b3)[lane];

    size_t base = (size_t)w * 64 + lane * 2;
    uint32_t H0 = x2hi[base], H1 = x2hi[base + 1];
    uint32_t L0 = x2lo[base], L1 = x2lo[base + 1];

    float y[4];
    y[0] = fmaxf(fmaxf(fmaf(acc.x, r, bb.x), 0.0f) + (bf_lo(H0) + bf_lo(L0)), 0.0f);
    y[1] = fmaxf(fmaxf(fmaf(acc.y, r, bb.y), 0.0f) + (bf_hi(H0) + bf_hi(L0)), 0.0f);
    y[2] = fmaxf(fmaxf(fmaf(acc.z, r, bb.z), 0.0f) + (bf_lo(H1) + bf_lo(L1)), 0.0f);
    y[3] = fmaxf(fmaxf(fmaf(acc.w, r, bb.w), 0.0f) + (bf_hi(H1) + bf_hi(L1)), 0.0f);

    float p0[4] = {0.f, 0.f, 0.f, 0.f};
    float p1[4] = {0.f, 0.f, 0.f, 0.f};
#pragma unroll
    for (int c2 = 0; c2 < 4; ++c2) {
#pragma unroll
        for (int kk = 0; kk < 32; ++kk) {
            float yv = __shfl_sync(0xffffffffu, y[c2], kk);
            int k = kk * 4 + c2;
            p0[c2] = fmaf(yv, Ws[k * OUTF + lane], p0[c2]);
            if (lane < OUTF - 32) p1[c2] = fmaf(yv, Ws[k * OUTF + 32 + lane], p1[c2]);
        }
    }
    out[(size_t)w * OUTF + lane] = (p0[0] + p0[1]) + (p0[2] + p0[3]) + bs[lane];
    if (lane < OUTF - 32)
        out[(size_t)w * OUTF + 32 + lane] =
            (p1[0] + p1[1]) + (p1[2] + p1[3]) + bs[32 + lane];
}

// ---------------- launcher ---------------------------------------------------
extern "C" void kernel_launch(void* const* d_in, const int* in_sizes, int n_in,
                              void* d_out, int out_size) {
    const float* feat = (const float*)d_in[0];
    const int*   src  = (const int*)  d_in[1];
    const int*   dst  = (const int*)  d_in[2];
    const float* W1   = (const float*)d_in[3];
    const float* b1   = (const float*)d_in[4];
    const float* W2   = (const float*)d_in[5];
    const float* b2   = (const float*)d_in[6];
    const float* W3   = (const float*)d_in[7];
    const float* b3   = (const float*)d_in[8];
    const float* Wfc  = (const float*)d_in[9];
    const float* bfc  = (const float*)d_in[10];
    float* out = (float*)d_out;

    float *h, *rout, *rout1, *rin;
    int *counts, *row_start, *esrc;
    uint32_t* w1t;
    __nv_bfloat16 *xhi, *xlo, *x2hi, *x2lo, *w2h, *w2l, *w3h, *w3l;
    cudaGetSymbolAddress((void**)&h,    g_h);
    cudaGetSymbolAddress((void**)&xhi,  g_xhi);
    cudaGetSymbolAddress((void**)&xlo,  g_xlo);
    cudaGetSymbolAddress((void**)&x2hi, g_x2hi);
    cudaGetSymbolAddress((void**)&x2lo, g_x2lo);
    cudaGetSymbolAddress((void**)&w1t,  g_w1t);
    cudaGetSymbolAddress((void**)&w2h,  g_w2hi);
    cudaGetSymbolAddress((void**)&w2l,  g_w2lo);
    cudaGetSymbolAddress((void**)&w3h,  g_w3hi);
    cudaGetSymbolAddress((void**)&w3l,  g_w3lo);
    cudaGetSymbolAddress((void**)&counts,    g_counts);
    cudaGetSymbolAddress((void**)&row_start, g_row_start);
    cudaGetSymbolAddress((void**)&esrc, g_esrc);
    cudaGetSymbolAddress((void**)&rout,  g_rout);
    cudaGetSymbolAddress((void**)&rout1, g_rout1);
    cudaGetSymbolAddress((void**)&rin,   g_rin);

    int* cout_  = counts;
    int* cin_   = counts + NN;
    int* cursor = counts + 2 * NN;

    cudaFuncSetAttribute(gemm_tf32_kernel, cudaFuncAttributeMaxDynamicSharedMemorySize, TSMEM);
    cudaFuncSetAttribute(gemm_bf16_kernel, cudaFuncAttributeMaxDynamicSharedMemorySize, BSMEM);

    const int gemm_grid   = (NN + GBM - 1) / GBM;   // 391
    const int gather_grid = (NN * 32 + 255) / 256;

    cudaMemsetAsync(counts, 0, 3 * NN * sizeof(int));
    // k1: degree count + W1 prep (independent halves, one launch)
    fat_count_prepw1<<<CNT_GRID + PW1_GRID, 256>>>(src, dst, cout_, cin_, W1, w1t);
    // k2: scan (block 0) + rinv (blocks 1..)
    scan_rinv_kernel<<<1 + (NN + 1023) / 1024, 1024>>>(cin_, cout_, row_start,
                                                       rout, rout1, rin);
    // k3: CSR fill + W2/W3 prep (independent halves, one launch)
    fat_fill_prepw23<<<CNT_GRID + PW23_GRID, 256>>>(src, dst, row_start, cursor, esrc,
                                                    W2, W3, w2h, w2l, w3h, w3l);

    // k4 <- profiled: layer-1 tf32 GEMM (parity-split loader; expect ~94 us)
    gemm_tf32_kernel<<<gemm_grid, 256, TSMEM>>>(feat, w1t, rout1, h, NN);

    gather_kernel<<<gather_grid, 256>>>(h, esrc, row_start, rin, b1,
                                        (uint32_t*)xhi, (uint32_t*)xlo);

    // layer 2 (split-bf16; x2 hi/lo doubles as residual branch for the FC head)
    gemm_bf16_kernel<<<gemm_grid, 256, BSMEM>>>(xhi, xlo, w2h, w2l, rout, h);
    gather_kernel<<<gather_grid, 256>>>(h, esrc, row_start, rin, b2,
                                        (uint32_t*)x2hi, (uint32_t*)x2lo);

    // layer 3
    gemm_bf16_kernel<<<gemm_grid, 256, BSMEM>>>(x2hi, x2lo, w3h, w3l, rout, h);

    // gather 3 + residual + FC head fused (one node per warp)
    gather_fc_kernel<<<(NN + 7) / 8, 256>>>(h, esrc, row_start, rin, b3,
                                            (const uint32_t*)x2hi, (const uint32_t*)x2lo,
                                            Wfc, bfc, out);
}